// round 6
// baseline (speedup 1.0000x reference)
#include <cuda_runtime.h>

#define T_STEPS 2048
#define BATCH   32
#define HID     256
#define INP     256
#define NRANK   4            // CTAs per batch (cluster size)
#define HLOC    (HID/NRANK)  // 64 hidden units per CTA

// Small scratch only (allocation-free rule: __device__ globals)
__device__ float g_WrT[HID * HID];   // W_rec transposed: [src][dst]
__device__ float g_WiT[INP * HID];   // W_in transposed:  [k][n]

// ---------------------------------------------------------------------------
// Transpose both weight matrices (tiny, one-time)
// ---------------------------------------------------------------------------
__global__ void transpose_weights(const float* __restrict__ Wi,
                                  const float* __restrict__ Wr) {
    int s = blockIdx.x;   // source (column) index
    int h = threadIdx.x;  // dest row index
    g_WiT[s * HID + h] = Wi[h * INP + s];
    g_WrT[s * HID + h] = Wr[h * HID + s];
}

// ---------------------------------------------------------------------------
// SGEMM: C = input(T*B,256) @ WiT(256,256), written into d_out spike region
// (in-place reuse: scan reads xw[t,b,h] before overwriting out[t,b,h]).
// ---------------------------------------------------------------------------
__global__ __launch_bounds__(256) void sgemm_xw(const float* __restrict__ A,
                                                float* __restrict__ C) {
    __shared__ float As[2][8][128];
    __shared__ float Bs[2][8][128];

    const int tid = threadIdx.x;
    const int tx = tid & 15;
    const int ty = tid >> 4;
    const int bm = blockIdx.x * 128;
    const int bn = blockIdx.y * 128;

    const int arow = tid >> 1;
    const int acol = (tid & 1) * 4;
    const int brow = tid >> 5;
    const int bcol = (tid & 31) * 4;

    const float* Ap = A + (size_t)(bm + arow) * INP + acol;
    const float* Bp = g_WiT + brow * HID + bn + bcol;

    float4 a = *(const float4*)Ap;
    float4 b = *(const float4*)Bp;
    As[0][acol + 0][arow] = a.x;
    As[0][acol + 1][arow] = a.y;
    As[0][acol + 2][arow] = a.z;
    As[0][acol + 3][arow] = a.w;
    *(float4*)&Bs[0][brow][bcol] = b;
    __syncthreads();

    float acc[8][8];
#pragma unroll
    for (int i = 0; i < 8; ++i)
#pragma unroll
        for (int j = 0; j < 8; ++j) acc[i][j] = 0.0f;

    for (int kt = 0; kt < 32; ++kt) {
        const int cur = kt & 1;
        float4 an, bn4;
        if (kt < 31) {
            an  = *(const float4*)(Ap + (kt + 1) * 8);
            bn4 = *(const float4*)(Bp + (size_t)(kt + 1) * 8 * HID);
        }
#pragma unroll
        for (int k = 0; k < 8; ++k) {
            float4 a0 = *(const float4*)&As[cur][k][ty * 4];
            float4 a1 = *(const float4*)&As[cur][k][64 + ty * 4];
            float4 b0 = *(const float4*)&Bs[cur][k][tx * 4];
            float4 b1 = *(const float4*)&Bs[cur][k][64 + tx * 4];
            float av[8] = {a0.x, a0.y, a0.z, a0.w, a1.x, a1.y, a1.z, a1.w};
            float bv[8] = {b0.x, b0.y, b0.z, b0.w, b1.x, b1.y, b1.z, b1.w};
#pragma unroll
            for (int i = 0; i < 8; ++i)
#pragma unroll
                for (int j = 0; j < 8; ++j)
                    acc[i][j] = fmaf(av[i], bv[j], acc[i][j]);
        }
        if (kt < 31) {
            const int nxt = cur ^ 1;
            As[nxt][acol + 0][arow] = an.x;
            As[nxt][acol + 1][arow] = an.y;
            As[nxt][acol + 2][arow] = an.z;
            As[nxt][acol + 3][arow] = an.w;
            *(float4*)&Bs[nxt][brow][bcol] = bn4;
        }
        __syncthreads();
    }

#pragma unroll
    for (int i = 0; i < 8; ++i) {
        const int row = bm + ((i < 4) ? (ty * 4 + i) : (64 + ty * 4 + (i - 4)));
        float4 c0 = {acc[i][0], acc[i][1], acc[i][2], acc[i][3]};
        float4 c1 = {acc[i][4], acc[i][5], acc[i][6], acc[i][7]};
        *(float4*)&C[(size_t)row * HID + bn + tx * 4]      = c0;
        *(float4*)&C[(size_t)row * HID + bn + 64 + tx * 4] = c1;
    }
}

// ---------------------------------------------------------------------------
// DSMEM helpers
// ---------------------------------------------------------------------------
__device__ __forceinline__ unsigned smem_u32(const void* p) {
    return (unsigned)__cvta_generic_to_shared(p);
}
__device__ __forceinline__ void st_local_u64(unsigned la, unsigned long long v) {
    asm volatile("st.volatile.shared.u64 [%0], %1;" :: "r"(la), "l"(v) : "memory");
}
__device__ __forceinline__ void st_remote_u64(unsigned la, unsigned rank,
                                              unsigned long long v) {
    unsigned ra;
    asm volatile("mapa.shared::cluster.u32 %0, %1, %2;" : "=r"(ra) : "r"(la), "r"(rank));
    asm volatile("st.relaxed.cluster.shared::cluster.u64 [%0], %1;"
                 :: "r"(ra), "l"(v) : "memory");
}
__device__ __forceinline__ void ld_vol_u64(unsigned la, unsigned& lo, unsigned& hi) {
    asm volatile("ld.volatile.shared.v2.u32 {%0,%1}, [%2];"
                 : "=r"(lo), "=r"(hi) : "r"(la));
}

// ---------------------------------------------------------------------------
// LIF scan, cluster of 4 CTAs per batch. CTA rank r owns h in [64r, 64r+64).
// Per step: ballot -> tagged mask broadcast to all 4 CTAs via DSMEM (double-
// buffered by stage=t&1; tag=t+1; spin-wait on volatile loads) -> 8 expander
// threads build compact spike lists -> scalar LDG.32 gather of this CTA's
// 64-float row segments (per-SM LDG issue count 4x lower than 1-CTA version).
// Overwrite safety: a writer reaches step t+2 (same stage) only after all
// CTAs published step-t+1 masks, which they do only after finishing all
// stage-t reads.
// ---------------------------------------------------------------------------
__global__ __launch_bounds__(64, 1) __cluster_dims__(NRANK, 1, 1)
void lif_scan(
    const float* __restrict__ z0, const float* __restrict__ v0,
    const float* __restrict__ i0,
    float* __restrict__ out, float* __restrict__ zf,
    float* __restrict__ vf, float* __restrict__ sf)
{
    const int cid   = blockIdx.x;        // 0..127
    const int b     = cid >> 2;          // batch
    const unsigned rank = cid & 3;       // cluster rank
    const int tid   = threadIdx.x;       // 0..63
    const int lane  = tid & 31;
    const int wloc  = tid >> 5;          // local warp 0/1
    const int word  = (int)rank * 2 + wloc;  // my mask word 0..7
    const int hg    = (int)rank * HLOC + tid; // global hidden index

    __shared__ unsigned long long buf[2][8];   // [stage][word] = {tag,mask}
    __shared__ unsigned short     slist[8][32];
    __shared__ int                cnt[8];

    if (tid < 16) ((unsigned long long*)buf)[tid] = 0ULL;  // tag 0 != any t+1
    __syncthreads();
    asm volatile("barrier.cluster.arrive.aligned;" ::: "memory");
    asm volatile("barrier.cluster.wait.aligned;"   ::: "memory");

    float v   = v0[b * HID + hg];
    float syn = i0[b * HID + hg];
    float z   = z0[b * HID + hg];

    float* xop = out + b * HID + hg;           // xw in, spikes out (in place)
    const float* wcol = g_WrT + hg;            // column hg of WrT rows

    const unsigned myslot[2] = { smem_u32(&buf[0][word]), smem_u32(&buf[1][word]) };
    const unsigned pollslot[2] = { smem_u32(&buf[0][tid & 7]), smem_u32(&buf[1][tid & 7]) };

    float xw_next = xop[0];

    for (int t = 0; t < T_STEPS; ++t) {
        const int      stage = t & 1;
        const unsigned tag   = (unsigned)(t + 1);

        const unsigned m = __ballot_sync(0xffffffffu, z > 0.0f);
        if (lane == 0) {
            const unsigned long long val =
                ((unsigned long long)tag << 32) | (unsigned long long)m;
            st_local_u64(myslot[stage], val);
#pragma unroll
            for (unsigned p = 0; p < NRANK; ++p)
                if (p != rank) st_remote_u64(myslot[stage], p, val);
        }

        const float xw_cur = xw_next;
        if (t + 1 < T_STEPS)
            xw_next = xop[(size_t)(t + 1) * (BATCH * HID)];  // overlaps exchange

        // wait for all 8 mask words of this step
        {
            unsigned lo, hi;
            do { ld_vol_u64(pollslot[stage], lo, hi); } while (hi != tag);
        }
        __syncthreads();

        // expand masks -> compact per-word spike lists
        if (tid < 8) {
            unsigned mm = (unsigned)(buf[stage][tid] & 0xffffffffULL);
            int k = 0;
            const int base = tid * 32;
            while (mm) {
                const int bit = __ffs(mm) - 1;
                mm &= mm - 1;
                slist[tid][k++] = (unsigned short)(base + bit);
            }
            cnt[tid] = k;
        }
        __syncthreads();

        // scalar gather: this CTA's 64-wide segment of each spiking row
        float r0 = 0.0f, r1 = 0.0f, r2 = 0.0f, r3 = 0.0f;
#pragma unroll
        for (int w = 0; w < 8; ++w) {
            const int c = cnt[w];
            int j = 0;
            for (; j + 4 <= c; j += 4) {
                const int s0 = slist[w][j],     s1 = slist[w][j + 1];
                const int s2 = slist[w][j + 2], s3 = slist[w][j + 3];
                r0 += __ldg(wcol + s0 * HID);
                r1 += __ldg(wcol + s1 * HID);
                r2 += __ldg(wcol + s2 * HID);
                r3 += __ldg(wcol + s3 * HID);
            }
            for (; j < c; ++j) r0 += __ldg(wcol + slist[w][j] * HID);
        }
        const float rec = (r0 + r1) + (r2 + r3);

        // LIF update (reference op order; no FMA contraction)
        const float vdec = __fadd_rn(v, __fmul_rn(0.1f, __fadd_rn(__fsub_rn(0.0f, v), syn)));
        const float idec = __fsub_rn(syn, __fmul_rn(0.2f, syn));
        const float zn   = (vdec - 1.0f > 0.0f) ? 1.0f : 0.0f;
        v   = (zn > 0.0f) ? 0.0f : vdec;
        syn = __fadd_rn(__fadd_rn(idec, xw_cur), rec);

        xop[(size_t)t * (BATCH * HID)] = zn;   // overwrite xw with spike
        z = zn;
    }

    zf[b * HID + hg] = z;
    vf[b * HID + hg] = v;
    sf[b * HID + hg] = syn;

    // keep smem alive until all peers' final stores have been consumed
    asm volatile("barrier.cluster.arrive.aligned;" ::: "memory");
    asm volatile("barrier.cluster.wait.aligned;"   ::: "memory");
}

// ---------------------------------------------------------------------------
extern "C" void kernel_launch(void* const* d_in, const int* in_sizes, int n_in,
                              void* d_out, int out_size) {
    const float* input = (const float*)d_in[0];  // (T, B, IN)
    const float* z0    = (const float*)d_in[1];  // (B, H)
    const float* v0    = (const float*)d_in[2];
    const float* i0    = (const float*)d_in[3];
    const float* Wi    = (const float*)d_in[4];  // (H, IN)
    const float* Wr    = (const float*)d_in[5];  // (H, H)

    float* out = (float*)d_out;                         // (T, B, H) spikes
    float* zf  = out + (size_t)T_STEPS * BATCH * HID;   // (B, H)
    float* vf  = zf + BATCH * HID;
    float* sf  = vf + BATCH * HID;

    transpose_weights<<<HID, HID>>>(Wi, Wr);
    sgemm_xw<<<dim3((T_STEPS * BATCH) / 128, HID / 128), 256>>>(input, out);
    lif_scan<<<BATCH * NRANK, 64>>>(z0, v0, i0, out, zf, vf, sf);
}

// round 7
// speedup vs baseline: 2.0553x; 2.0553x over previous
#include <cuda_runtime.h>

#define T_STEPS 2048
#define BATCH   32
#define HID     256
#define INP     256
#define HSM     160   // hidden columns cached in shared memory (160KB)

// Small scratch only (allocation-free rule: __device__ globals)
__device__ float g_WrT[HID * HID];   // W_rec transposed: [src][dst]
__device__ float g_WiT[INP * HID];   // W_in transposed:  [k][n]

// ---------------------------------------------------------------------------
// Transpose both weight matrices (tiny, one-time)
// ---------------------------------------------------------------------------
__global__ void transpose_weights(const float* __restrict__ Wi,
                                  const float* __restrict__ Wr) {
    int s = blockIdx.x;   // source (column) index
    int h = threadIdx.x;  // dest row index
    g_WiT[s * HID + h] = Wi[h * INP + s];
    g_WrT[s * HID + h] = Wr[h * HID + s];
}

// ---------------------------------------------------------------------------
// SGEMM: C = input(T*B,256) @ WiT(256,256), written into d_out spike region
// (in-place reuse: scan reads xw[t,b,h] before overwriting out[t,b,h]).
// 128x128 block tile, k-step 8, double-buffered smem, 8x8 microtile.
// ---------------------------------------------------------------------------
__global__ __launch_bounds__(256) void sgemm_xw(const float* __restrict__ A,
                                                float* __restrict__ C) {
    __shared__ float As[2][8][128];
    __shared__ float Bs[2][8][128];

    const int tid = threadIdx.x;
    const int tx = tid & 15;
    const int ty = tid >> 4;
    const int bm = blockIdx.x * 128;
    const int bn = blockIdx.y * 128;

    const int arow = tid >> 1;
    const int acol = (tid & 1) * 4;
    const int brow = tid >> 5;
    const int bcol = (tid & 31) * 4;

    const float* Ap = A + (size_t)(bm + arow) * INP + acol;
    const float* Bp = g_WiT + brow * HID + bn + bcol;

    float4 a = *(const float4*)Ap;
    float4 b = *(const float4*)Bp;
    As[0][acol + 0][arow] = a.x;
    As[0][acol + 1][arow] = a.y;
    As[0][acol + 2][arow] = a.z;
    As[0][acol + 3][arow] = a.w;
    *(float4*)&Bs[0][brow][bcol] = b;
    __syncthreads();

    float acc[8][8];
#pragma unroll
    for (int i = 0; i < 8; ++i)
#pragma unroll
        for (int j = 0; j < 8; ++j) acc[i][j] = 0.0f;

    for (int kt = 0; kt < 32; ++kt) {
        const int cur = kt & 1;
        float4 an, bn4;
        if (kt < 31) {
            an  = *(const float4*)(Ap + (kt + 1) * 8);
            bn4 = *(const float4*)(Bp + (size_t)(kt + 1) * 8 * HID);
        }
#pragma unroll
        for (int k = 0; k < 8; ++k) {
            float4 a0 = *(const float4*)&As[cur][k][ty * 4];
            float4 a1 = *(const float4*)&As[cur][k][64 + ty * 4];
            float4 b0 = *(const float4*)&Bs[cur][k][tx * 4];
            float4 b1 = *(const float4*)&Bs[cur][k][64 + tx * 4];
            float av[8] = {a0.x, a0.y, a0.z, a0.w, a1.x, a1.y, a1.z, a1.w};
            float bv[8] = {b0.x, b0.y, b0.z, b0.w, b1.x, b1.y, b1.z, b1.w};
#pragma unroll
            for (int i = 0; i < 8; ++i)
#pragma unroll
                for (int j = 0; j < 8; ++j)
                    acc[i][j] = fmaf(av[i], bv[j], acc[i][j]);
        }
        if (kt < 31) {
            const int nxt = cur ^ 1;
            As[nxt][acol + 0][arow] = an.x;
            As[nxt][acol + 1][arow] = an.y;
            As[nxt][acol + 2][arow] = an.z;
            As[nxt][acol + 3][arow] = an.w;
            *(float4*)&Bs[nxt][brow][bcol] = bn4;
        }
        __syncthreads();
    }

#pragma unroll
    for (int i = 0; i < 8; ++i) {
        const int row = bm + ((i < 4) ? (ty * 4 + i) : (64 + ty * 4 + (i - 4)));
        float4 c0 = {acc[i][0], acc[i][1], acc[i][2], acc[i][3]};
        float4 c1 = {acc[i][4], acc[i][5], acc[i][6], acc[i][7]};
        *(float4*)&C[(size_t)row * HID + bn + tx * 4]      = c0;
        *(float4*)&C[(size_t)row * HID + bn + 64 + tx * 4] = c1;
    }
}

// ---------------------------------------------------------------------------
// LIF scan: one block per batch, 256 threads = one per hidden unit.
// Identical skeleton to the proven R3 version (ballot -> prefix -> compact
// spike list -> scalar gather -> update). Only change: columns h<HSM are
// gathered from a 160KB smem-resident copy of W_recT (crossbar path),
// columns h>=HSM via LDG (L1 path) -> the two load paths drain in parallel.
// ---------------------------------------------------------------------------
__global__ __launch_bounds__(256) void lif_scan(
    const float* __restrict__ z0, const float* __restrict__ v0,
    const float* __restrict__ i0,
    float* __restrict__ out, float* __restrict__ zf,
    float* __restrict__ vf, float* __restrict__ sf)
{
    extern __shared__ float Wsm[];   // [256][HSM]

    const int b = blockIdx.x;
    const int h = threadIdx.x;
    const int lane = h & 31;
    const int wid  = h >> 5;

    __shared__ unsigned       masks[8];
    __shared__ unsigned short slist[256];

    // preload W_recT columns [0, HSM) for all 256 rows (float4, coalesced)
    for (int d = h * 4; d < HID * HSM; d += 256 * 4) {
        const int row = d / HSM, col = d % HSM;
        *(float4*)&Wsm[d] = *(const float4*)&g_WrT[row * HID + col];
    }
    __syncthreads();

    float v   = v0[b * HID + h];
    float syn = i0[b * HID + h];
    float z   = z0[b * HID + h];

    float*       xop = out + b * HID + h;   // xw in, spikes out (in place)
    const float* wr  = g_WrT + h;

    for (int t = 0; t < T_STEPS; ++t) {
        const unsigned m = __ballot_sync(0xffffffffu, z > 0.0f);
        const float xwv = xop[(size_t)t * (BATCH * HID)];   // load early
        if (lane == 0) masks[wid] = m;
        __syncthreads();

        int base = 0, total = 0;
#pragma unroll
        for (int w = 0; w < 8; ++w) {
            const int c = __popc(masks[w]);
            if (w < wid) base += c;
            total += c;
        }
        if (z > 0.0f)
            slist[base + __popc(m & ((1u << lane) - 1u))] = (unsigned short)h;
        __syncthreads();

        // sparse recurrent gather: rec = sum over spiking src of W_rec[h, src]
        float r0 = 0.0f, r1 = 0.0f, r2 = 0.0f, r3 = 0.0f;
        if (h < HSM) {
            const float* ws = Wsm + h;
            int j = 0;
            for (; j + 4 <= total; j += 4) {
                const int s0 = slist[j],     s1 = slist[j + 1];
                const int s2 = slist[j + 2], s3 = slist[j + 3];
                r0 += ws[s0 * HSM];
                r1 += ws[s1 * HSM];
                r2 += ws[s2 * HSM];
                r3 += ws[s3 * HSM];
            }
            for (; j < total; ++j) r0 += ws[slist[j] * HSM];
        } else {
            int j = 0;
            for (; j + 4 <= total; j += 4) {
                const int s0 = slist[j],     s1 = slist[j + 1];
                const int s2 = slist[j + 2], s3 = slist[j + 3];
                r0 += __ldg(wr + s0 * HID);
                r1 += __ldg(wr + s1 * HID);
                r2 += __ldg(wr + s2 * HID);
                r3 += __ldg(wr + s3 * HID);
            }
            for (; j < total; ++j) r0 += __ldg(wr + slist[j] * HID);
        }
        const float rec = (r0 + r1) + (r2 + r3);

        // LIF update (match reference op order; no FMA contraction)
        const float vdec = __fadd_rn(v, __fmul_rn(0.1f, __fadd_rn(__fsub_rn(0.0f, v), syn)));
        const float idec = __fsub_rn(syn, __fmul_rn(0.2f, syn));
        const float zn   = (vdec - 1.0f > 0.0f) ? 1.0f : 0.0f;
        v   = (zn > 0.0f) ? 0.0f : vdec;
        syn = __fadd_rn(__fadd_rn(idec, xwv), rec);

        xop[(size_t)t * (BATCH * HID)] = zn;   // overwrite xw with spike
        z = zn;
    }

    zf[b * HID + h] = z;
    vf[b * HID + h] = v;
    sf[b * HID + h] = syn;
}

// ---------------------------------------------------------------------------
extern "C" void kernel_launch(void* const* d_in, const int* in_sizes, int n_in,
                              void* d_out, int out_size) {
    const float* input = (const float*)d_in[0];  // (T, B, IN)
    const float* z0    = (const float*)d_in[1];  // (B, H)
    const float* v0    = (const float*)d_in[2];
    const float* i0    = (const float*)d_in[3];
    const float* Wi    = (const float*)d_in[4];  // (H, IN)
    const float* Wr    = (const float*)d_in[5];  // (H, H)

    float* out = (float*)d_out;                         // (T, B, H) spikes
    float* zf  = out + (size_t)T_STEPS * BATCH * HID;   // (B, H)
    float* vf  = zf + BATCH * HID;
    float* sf  = vf + BATCH * HID;

    const int smem_bytes = HID * HSM * (int)sizeof(float);   // 160 KB
    cudaFuncSetAttribute(lif_scan, cudaFuncAttributeMaxDynamicSharedMemorySize,
                         smem_bytes);

    transpose_weights<<<HID, HID>>>(Wi, Wr);
    sgemm_xw<<<dim3((T_STEPS * BATCH) / 128, HID / 128), 256>>>(input, out);
    lif_scan<<<BATCH, HID, smem_bytes>>>(z0, v0, i0, out, zf, vf, sf);
}

// round 8
// speedup vs baseline: 2.6488x; 1.2888x over previous
#include <cuda_runtime.h>

#define T_STEPS 2048
#define BATCH   32
#define HID     256
#define INP     256
#define HSM     160          // hidden columns cached in shared memory
#define NROW    257          // 256 sources + one all-zero pad row
#define PADIDX  256          // spike-list pad index -> zero row

// Small scratch only (allocation-free rule: __device__ globals)
__device__ float g_WrT[NROW * HID];  // W_rec transposed + zero row
__device__ float g_WiT[INP * HID];   // W_in transposed

// ---------------------------------------------------------------------------
// Transpose both weight matrices; block 0 also zeroes the pad row.
// ---------------------------------------------------------------------------
__global__ void transpose_weights(const float* __restrict__ Wi,
                                  const float* __restrict__ Wr) {
    int s = blockIdx.x;
    int h = threadIdx.x;
    g_WiT[s * HID + h] = Wi[h * INP + s];
    g_WrT[s * HID + h] = Wr[h * HID + s];
    if (s == 0) g_WrT[PADIDX * HID + h] = 0.0f;
}

// ---------------------------------------------------------------------------
// SGEMM: C = input(T*B,256) @ WiT(256,256) into d_out spike region (in-place
// reuse: scan reads xw[t,b,h] before overwriting out[t,b,h]).
// ---------------------------------------------------------------------------
__global__ __launch_bounds__(256) void sgemm_xw(const float* __restrict__ A,
                                                float* __restrict__ C) {
    __shared__ float As[2][8][128];
    __shared__ float Bs[2][8][128];

    const int tid = threadIdx.x;
    const int tx = tid & 15;
    const int ty = tid >> 4;
    const int bm = blockIdx.x * 128;
    const int bn = blockIdx.y * 128;

    const int arow = tid >> 1;
    const int acol = (tid & 1) * 4;
    const int brow = tid >> 5;
    const int bcol = (tid & 31) * 4;

    const float* Ap = A + (size_t)(bm + arow) * INP + acol;
    const float* Bp = g_WiT + brow * HID + bn + bcol;

    float4 a = *(const float4*)Ap;
    float4 b = *(const float4*)Bp;
    As[0][acol + 0][arow] = a.x;
    As[0][acol + 1][arow] = a.y;
    As[0][acol + 2][arow] = a.z;
    As[0][acol + 3][arow] = a.w;
    *(float4*)&Bs[0][brow][bcol] = b;
    __syncthreads();

    float acc[8][8];
#pragma unroll
    for (int i = 0; i < 8; ++i)
#pragma unroll
        for (int j = 0; j < 8; ++j) acc[i][j] = 0.0f;

    for (int kt = 0; kt < 32; ++kt) {
        const int cur = kt & 1;
        float4 an, bn4;
        if (kt < 31) {
            an  = *(const float4*)(Ap + (kt + 1) * 8);
            bn4 = *(const float4*)(Bp + (size_t)(kt + 1) * 8 * HID);
        }
#pragma unroll
        for (int k = 0; k < 8; ++k) {
            float4 a0 = *(const float4*)&As[cur][k][ty * 4];
            float4 a1 = *(const float4*)&As[cur][k][64 + ty * 4];
            float4 b0 = *(const float4*)&Bs[cur][k][tx * 4];
            float4 b1 = *(const float4*)&Bs[cur][k][64 + tx * 4];
            float av[8] = {a0.x, a0.y, a0.z, a0.w, a1.x, a1.y, a1.z, a1.w};
            float bv[8] = {b0.x, b0.y, b0.z, b0.w, b1.x, b1.y, b1.z, b1.w};
#pragma unroll
            for (int i = 0; i < 8; ++i)
#pragma unroll
                for (int j = 0; j < 8; ++j)
                    acc[i][j] = fmaf(av[i], bv[j], acc[i][j]);
        }
        if (kt < 31) {
            const int nxt = cur ^ 1;
            As[nxt][acol + 0][arow] = an.x;
            As[nxt][acol + 1][arow] = an.y;
            As[nxt][acol + 2][arow] = an.z;
            As[nxt][acol + 3][arow] = an.w;
            *(float4*)&Bs[nxt][brow][bcol] = bn4;
        }
        __syncthreads();
    }

#pragma unroll
    for (int i = 0; i < 8; ++i) {
        const int row = bm + ((i < 4) ? (ty * 4 + i) : (64 + ty * 4 + (i - 4)));
        float4 c0 = {acc[i][0], acc[i][1], acc[i][2], acc[i][3]};
        float4 c1 = {acc[i][4], acc[i][5], acc[i][6], acc[i][7]};
        *(float4*)&C[(size_t)row * HID + bn + tx * 4]      = c0;
        *(float4*)&C[(size_t)row * HID + bn + 64 + tx * 4] = c1;
    }
}

// ---------------------------------------------------------------------------
// LIF scan: one block per batch, 256 threads = one per hidden unit.
// Hybrid gather: warps 0-4 (h<160) read a smem copy of W columns [0,160);
// warps 5-7 read W columns [160,256) via LDG. Spike list padded to a
// multiple of 16 with the zero-row index -> branch-free software-pipelined
// gather loops (1-deep prefetch for LDS, 2-deep for LDG).
// ---------------------------------------------------------------------------
__global__ __launch_bounds__(256) void lif_scan(
    const float* __restrict__ z0, const float* __restrict__ v0,
    const float* __restrict__ i0,
    float* __restrict__ out, float* __restrict__ zf,
    float* __restrict__ vf, float* __restrict__ sf)
{
    extern __shared__ float Wsm[];   // [NROW][HSM]

    const int b = blockIdx.x;
    const int h = threadIdx.x;
    const int lane = h & 31;
    const int wid  = h >> 5;

    __shared__ unsigned       masks[8];
    __shared__ unsigned short slist[272];   // 256 + 15 pad (rounded)

    // preload W columns [0,HSM) for all 257 rows (incl. zero row), float4
    for (int d = h * 4; d < NROW * HSM; d += 256 * 4) {
        const int row = d / HSM, col = d % HSM;
        *(float4*)&Wsm[d] = *(const float4*)&g_WrT[row * HID + col];
    }
    __syncthreads();

    float v   = v0[b * HID + h];
    float syn = i0[b * HID + h];
    float z   = z0[b * HID + h];

    float*       xop = out + b * HID + h;   // xw in, spikes out (in place)
    const float* wr  = g_WrT + h;

    for (int t = 0; t < T_STEPS; ++t) {
        const unsigned m = __ballot_sync(0xffffffffu, z > 0.0f);
        const float xwv = xop[(size_t)t * (BATCH * HID)];   // load early
        if (lane == 0) masks[wid] = m;
        __syncthreads();

        int base = 0, total = 0;
#pragma unroll
        for (int w = 0; w < 8; ++w) {
            const int c = __popc(masks[w]);
            if (w < wid) base += c;
            total += c;
        }
        if (z > 0.0f)
            slist[base + __popc(m & ((1u << lane) - 1u))] = (unsigned short)h;
        if (h < 15)
            slist[total + h] = (unsigned short)PADIDX;     // zero-row pads
        const int padded = (total + 15) & ~15;
        __syncthreads();

        float r0 = 0.f, r1 = 0.f, r2 = 0.f, r3 = 0.f;
        float r4 = 0.f, r5 = 0.f, r6 = 0.f, r7 = 0.f;

        if (h < HSM) {
            // LDS path, 1-deep prefetch (8 in flight)
            const float* ws = Wsm + h;
            if (padded) {
                float v0_, v1_, v2_, v3_, v4_, v5_, v6_, v7_;
                v0_ = ws[slist[0] * HSM]; v1_ = ws[slist[1] * HSM];
                v2_ = ws[slist[2] * HSM]; v3_ = ws[slist[3] * HSM];
                v4_ = ws[slist[4] * HSM]; v5_ = ws[slist[5] * HSM];
                v6_ = ws[slist[6] * HSM]; v7_ = ws[slist[7] * HSM];
                for (int j = 8; j < padded; j += 8) {
                    float n0 = ws[slist[j + 0] * HSM], n1 = ws[slist[j + 1] * HSM];
                    float n2 = ws[slist[j + 2] * HSM], n3 = ws[slist[j + 3] * HSM];
                    float n4 = ws[slist[j + 4] * HSM], n5 = ws[slist[j + 5] * HSM];
                    float n6 = ws[slist[j + 6] * HSM], n7 = ws[slist[j + 7] * HSM];
                    r0 += v0_; r1 += v1_; r2 += v2_; r3 += v3_;
                    r4 += v4_; r5 += v5_; r6 += v6_; r7 += v7_;
                    v0_ = n0; v1_ = n1; v2_ = n2; v3_ = n3;
                    v4_ = n4; v5_ = n5; v6_ = n6; v7_ = n7;
                }
                r0 += v0_; r1 += v1_; r2 += v2_; r3 += v3_;
                r4 += v4_; r5 += v5_; r6 += v6_; r7 += v7_;
            }
        } else {
            // LDG path, 2-deep prefetch (16 in flight)
            if (padded) {
                float a0, a1, a2, a3, a4, a5, a6, a7;
                float b0, b1, b2, b3, b4, b5, b6, b7;
                a0 = __ldg(wr + slist[0] * HID);  a1 = __ldg(wr + slist[1] * HID);
                a2 = __ldg(wr + slist[2] * HID);  a3 = __ldg(wr + slist[3] * HID);
                a4 = __ldg(wr + slist[4] * HID);  a5 = __ldg(wr + slist[5] * HID);
                a6 = __ldg(wr + slist[6] * HID);  a7 = __ldg(wr + slist[7] * HID);
                b0 = __ldg(wr + slist[8] * HID);  b1 = __ldg(wr + slist[9] * HID);
                b2 = __ldg(wr + slist[10] * HID); b3 = __ldg(wr + slist[11] * HID);
                b4 = __ldg(wr + slist[12] * HID); b5 = __ldg(wr + slist[13] * HID);
                b6 = __ldg(wr + slist[14] * HID); b7 = __ldg(wr + slist[15] * HID);
                for (int j = 16; j < padded; j += 8) {
                    float n0 = __ldg(wr + slist[j + 0] * HID);
                    float n1 = __ldg(wr + slist[j + 1] * HID);
                    float n2 = __ldg(wr + slist[j + 2] * HID);
                    float n3 = __ldg(wr + slist[j + 3] * HID);
                    float n4 = __ldg(wr + slist[j + 4] * HID);
                    float n5 = __ldg(wr + slist[j + 5] * HID);
                    float n6 = __ldg(wr + slist[j + 6] * HID);
                    float n7 = __ldg(wr + slist[j + 7] * HID);
                    r0 += a0; r1 += a1; r2 += a2; r3 += a3;
                    r4 += a4; r5 += a5; r6 += a6; r7 += a7;
                    a0 = b0; a1 = b1; a2 = b2; a3 = b3;
                    a4 = b4; a5 = b5; a6 = b6; a7 = b7;
                    b0 = n0; b1 = n1; b2 = n2; b3 = n3;
                    b4 = n4; b5 = n5; b6 = n6; b7 = n7;
                }
                r0 += a0; r1 += a1; r2 += a2; r3 += a3;
                r4 += a4; r5 += a5; r6 += a6; r7 += a7;
                r0 += b0; r1 += b1; r2 += b2; r3 += b3;
                r4 += b4; r5 += b5; r6 += b6; r7 += b7;
            }
        }
        const float rec = ((r0 + r1) + (r2 + r3)) + ((r4 + r5) + (r6 + r7));

        // LIF update (match reference op order; no FMA contraction)
        const float vdec = __fadd_rn(v, __fmul_rn(0.1f, __fadd_rn(__fsub_rn(0.0f, v), syn)));
        const float idec = __fsub_rn(syn, __fmul_rn(0.2f, syn));
        const float zn   = (vdec - 1.0f > 0.0f) ? 1.0f : 0.0f;
        v   = (zn > 0.0f) ? 0.0f : vdec;
        syn = __fadd_rn(__fadd_rn(idec, xwv), rec);

        xop[(size_t)t * (BATCH * HID)] = zn;   // overwrite xw with spike
        z = zn;
    }

    zf[b * HID + h] = z;
    vf[b * HID + h] = v;
    sf[b * HID + h] = syn;
}

// ---------------------------------------------------------------------------
extern "C" void kernel_launch(void* const* d_in, const int* in_sizes, int n_in,
                              void* d_out, int out_size) {
    const float* input = (const float*)d_in[0];  // (T, B, IN)
    const float* z0    = (const float*)d_in[1];  // (B, H)
    const float* v0    = (const float*)d_in[2];
    const float* i0    = (const float*)d_in[3];
    const float* Wi    = (const float*)d_in[4];  // (H, IN)
    const float* Wr    = (const float*)d_in[5];  // (H, H)

    float* out = (float*)d_out;                         // (T, B, H) spikes
    float* zf  = out + (size_t)T_STEPS * BATCH * HID;   // (B, H)
    float* vf  = zf + BATCH * HID;
    float* sf  = vf + BATCH * HID;

    const int smem_bytes = NROW * HSM * (int)sizeof(float);   // ~161 KB
    cudaFuncSetAttribute(lif_scan, cudaFuncAttributeMaxDynamicSharedMemorySize,
                         smem_bytes);

    transpose_weights<<<HID, HID>>>(Wi, Wr);
    sgemm_xw<<<dim3((T_STEPS * BATCH) / 128, HID / 128), 256>>>(input, out);
    lif_scan<<<BATCH, HID, smem_bytes>>>(z0, v0, i0, out, zf, vf, sf);
}

// round 9
// speedup vs baseline: 3.1098x; 1.1740x over previous
#include <cuda_runtime.h>

#define T_STEPS 2048
#define BATCH   32
#define HID     256
#define INP     256
#define HSM     160          // hidden columns cached in shared memory
#define NROW    257          // 256 sources + one all-zero pad row
#define PADIDX  256          // spike-list pad index -> zero row
#define NSCAN   32           // scan CTAs (== BATCH), scheduled first
#define GEMM_CTAS 1024       // 512 bm-tiles x 2 bn-tiles
#define NCHUNK  32           // 2048 steps / 64 per chunk
#define CTAS_PER_CHUNK 32    // 16 bm-tiles x 2 bn-tiles per 64 steps

// Scratch (allocation-free rule: __device__ globals)
__device__ float g_WrT[NROW * HID];  // W_rec transposed + zero row
__device__ float g_WiT[INP * HID];   // W_in transposed
__device__ int   g_cnt[NCHUNK];      // GEMM chunk-completion counters

// ---------------------------------------------------------------------------
// Transpose weights; also zero pad row and chunk counters (runs each replay
// before the fused kernel -> counters reset for every graph execution).
// ---------------------------------------------------------------------------
__global__ void transpose_weights(const float* __restrict__ Wi,
                                  const float* __restrict__ Wr) {
    int s = blockIdx.x;
    int h = threadIdx.x;
    g_WiT[s * HID + h] = Wi[h * INP + s];
    g_WrT[s * HID + h] = Wr[h * HID + s];
    if (s == 0) {
        g_WrT[PADIDX * HID + h] = 0.0f;
        if (h < NCHUNK) g_cnt[h] = 0;
    }
}

// ---------------------------------------------------------------------------
// GEMM body: one 128x128 tile of C = input(T*B,256) @ WiT. C == d_out spike
// region (in-place reuse). After storing, bump this tile's chunk counter.
// Uses first 16KB of dynamic smem.
// ---------------------------------------------------------------------------
__device__ void gemm_body(float* sm, int gbid,
                          const float* __restrict__ A, float* __restrict__ C) {
    float* As = sm;           // [2][8][128]
    float* Bs = sm + 2048;    // [2][8][128]

    const int tid = threadIdx.x;
    const int tx = tid & 15;
    const int ty = tid >> 4;
    const int bmt = gbid >> 1;           // 0..511 (t-ordered)
    const int bm  = bmt * 128;
    const int bn  = (gbid & 1) * 128;

    const int arow = tid >> 1;
    const int acol = (tid & 1) * 4;
    const int brow = tid >> 5;
    const int bcol = (tid & 31) * 4;

    const float* Ap = A + (size_t)(bm + arow) * INP + acol;
    const float* Bp = g_WiT + brow * HID + bn + bcol;

    float4 a = *(const float4*)Ap;
    float4 b = *(const float4*)Bp;
    As[(acol + 0) * 128 + arow] = a.x;
    As[(acol + 1) * 128 + arow] = a.y;
    As[(acol + 2) * 128 + arow] = a.z;
    As[(acol + 3) * 128 + arow] = a.w;
    *(float4*)&Bs[brow * 128 + bcol] = b;
    __syncthreads();

    float acc[8][8];
#pragma unroll
    for (int i = 0; i < 8; ++i)
#pragma unroll
        for (int j = 0; j < 8; ++j) acc[i][j] = 0.0f;

    for (int kt = 0; kt < 32; ++kt) {
        const int cur = (kt & 1) * 1024;
        float4 an, bn4;
        if (kt < 31) {
            an  = *(const float4*)(Ap + (kt + 1) * 8);
            bn4 = *(const float4*)(Bp + (size_t)(kt + 1) * 8 * HID);
        }
#pragma unroll
        for (int k = 0; k < 8; ++k) {
            float4 a0 = *(const float4*)&As[cur + k * 128 + ty * 4];
            float4 a1 = *(const float4*)&As[cur + k * 128 + 64 + ty * 4];
            float4 b0 = *(const float4*)&Bs[cur + k * 128 + tx * 4];
            float4 b1 = *(const float4*)&Bs[cur + k * 128 + 64 + tx * 4];
            float av[8] = {a0.x, a0.y, a0.z, a0.w, a1.x, a1.y, a1.z, a1.w};
            float bv[8] = {b0.x, b0.y, b0.z, b0.w, b1.x, b1.y, b1.z, b1.w};
#pragma unroll
            for (int i = 0; i < 8; ++i)
#pragma unroll
                for (int j = 0; j < 8; ++j)
                    acc[i][j] = fmaf(av[i], bv[j], acc[i][j]);
        }
        if (kt < 31) {
            const int nxt = ((kt & 1) ^ 1) * 1024;
            As[nxt + (acol + 0) * 128 + arow] = an.x;
            As[nxt + (acol + 1) * 128 + arow] = an.y;
            As[nxt + (acol + 2) * 128 + arow] = an.z;
            As[nxt + (acol + 3) * 128 + arow] = an.w;
            *(float4*)&Bs[nxt + brow * 128 + bcol] = bn4;
        }
        __syncthreads();
    }

#pragma unroll
    for (int i = 0; i < 8; ++i) {
        const int row = bm + ((i < 4) ? (ty * 4 + i) : (64 + ty * 4 + (i - 4)));
        float4 c0 = {acc[i][0], acc[i][1], acc[i][2], acc[i][3]};
        float4 c1 = {acc[i][4], acc[i][5], acc[i][6], acc[i][7]};
        *(float4*)&C[(size_t)row * HID + bn + tx * 4]      = c0;
        *(float4*)&C[(size_t)row * HID + bn + 64 + tx * 4] = c1;
    }

    __threadfence();
    __syncthreads();
    if (tid == 0) atomicAdd(&g_cnt[bmt >> 4], 1);
}

// ---------------------------------------------------------------------------
// Scan body: one CTA per batch, 256 threads = one per hidden unit.
// Hybrid gather (warps 0-4 LDS from 164KB smem W copy, warps 5-7 LDG),
// vector ushort4 index loads, software-pipelined. Polls chunk counters
// every 64 steps to stay behind the GEMM producer.
// ---------------------------------------------------------------------------
__device__ void scan_body(float* Wsm,
    const float* __restrict__ z0, const float* __restrict__ v0,
    const float* __restrict__ i0,
    float* __restrict__ out, float* __restrict__ zf,
    float* __restrict__ vf, float* __restrict__ sf)
{
    const int b = blockIdx.x;
    const int h = threadIdx.x;
    const int lane = h & 31;
    const int wid  = h >> 5;

    __shared__ unsigned masks[8];
    __shared__ alignas(16) unsigned short slist[272];

    // preload W columns [0,HSM) for all 257 rows (incl. zero row), float4
    for (int d = h * 4; d < NROW * HSM; d += 256 * 4) {
        const int row = d / HSM, col = d % HSM;
        *(float4*)&Wsm[d] = *(const float4*)&g_WrT[row * HID + col];
    }

    float v   = v0[b * HID + h];
    float syn = i0[b * HID + h];
    float z   = z0[b * HID + h];

    float*       xop = out + b * HID + h;   // xw in, spikes out (in place)
    const float* wr  = g_WrT + h;

    for (int t = 0; t < T_STEPS; ++t) {
        if ((t & 63) == 0) {
            if (h == 0) {
                const int c = t >> 6;
                const volatile int* vc = g_cnt;
                while (vc[c] < CTAS_PER_CHUNK) __nanosleep(200);
                __threadfence();
            }
            __syncthreads();   // chunk ready (also covers Wsm preload at t=0)
        }

        const unsigned m = __ballot_sync(0xffffffffu, z > 0.0f);
        const float xwv = xop[(size_t)t * (BATCH * HID)];   // load early
        if (lane == 0) masks[wid] = m;
        __syncthreads();

        int base = 0, total = 0;
#pragma unroll
        for (int w = 0; w < 8; ++w) {
            const int c = __popc(masks[w]);
            if (w < wid) base += c;
            total += c;
        }
        if (z > 0.0f)
            slist[base + __popc(m & ((1u << lane) - 1u))] = (unsigned short)h;
        if (h < 15)
            slist[total + h] = (unsigned short)PADIDX;     // zero-row pads
        const int padded = (total + 15) & ~15;
        __syncthreads();

        float r[8];
#pragma unroll
        for (int q = 0; q < 8; ++q) r[q] = 0.0f;

        if (h < HSM) {
            // LDS path: 8-wide, 1-deep pipeline, ushort4 index loads
            const float* ws = Wsm + h;
            if (padded) {
                unsigned short idx[8];
                float val[8];
                *(ushort4*)&idx[0] = *(const ushort4*)&slist[0];
                *(ushort4*)&idx[4] = *(const ushort4*)&slist[4];
#pragma unroll
                for (int q = 0; q < 8; ++q) val[q] = ws[idx[q] * HSM];
                for (int j = 8; j < padded; j += 8) {
                    unsigned short ni[8];
                    float nv[8];
                    *(ushort4*)&ni[0] = *(const ushort4*)&slist[j];
                    *(ushort4*)&ni[4] = *(const ushort4*)&slist[j + 4];
#pragma unroll
                    for (int q = 0; q < 8; ++q) nv[q] = ws[ni[q] * HSM];
#pragma unroll
                    for (int q = 0; q < 8; ++q) r[q] += val[q];
#pragma unroll
                    for (int q = 0; q < 8; ++q) val[q] = nv[q];
                }
#pragma unroll
                for (int q = 0; q < 8; ++q) r[q] += val[q];
            }
        } else {
            // LDG path: 16-wide, 1-deep pipeline (16 loads in flight)
            if (padded) {
                unsigned short idx[16];
                float val[16];
#pragma unroll
                for (int q = 0; q < 4; ++q)
                    *(ushort4*)&idx[q * 4] = *(const ushort4*)&slist[q * 4];
#pragma unroll
                for (int q = 0; q < 16; ++q) val[q] = __ldg(wr + idx[q] * HID);
                for (int j = 16; j < padded; j += 16) {
                    unsigned short ni[16];
                    float nv[16];
#pragma unroll
                    for (int q = 0; q < 4; ++q)
                        *(ushort4*)&ni[q * 4] = *(const ushort4*)&slist[j + q * 4];
#pragma unroll
                    for (int q = 0; q < 16; ++q) nv[q] = __ldg(wr + ni[q] * HID);
#pragma unroll
                    for (int q = 0; q < 16; ++q) r[q & 7] += val[q];
#pragma unroll
                    for (int q = 0; q < 16; ++q) val[q] = nv[q];
                }
#pragma unroll
                for (int q = 0; q < 16; ++q) r[q & 7] += val[q];
            }
        }
        const float rec = ((r[0] + r[1]) + (r[2] + r[3])) +
                          ((r[4] + r[5]) + (r[6] + r[7]));

        // LIF update (match reference op order; no FMA contraction)
        const float vdec = __fadd_rn(v, __fmul_rn(0.1f, __fadd_rn(__fsub_rn(0.0f, v), syn)));
        const float idec = __fsub_rn(syn, __fmul_rn(0.2f, syn));
        const float zn   = (vdec - 1.0f > 0.0f) ? 1.0f : 0.0f;
        v   = (zn > 0.0f) ? 0.0f : vdec;
        syn = __fadd_rn(__fadd_rn(idec, xwv), rec);

        xop[(size_t)t * (BATCH * HID)] = zn;   // overwrite xw with spike
        z = zn;
    }

    zf[b * HID + h] = z;
    vf[b * HID + h] = v;
    sf[b * HID + h] = syn;
}

// ---------------------------------------------------------------------------
// Fused kernel: blocks 0..31 = per-batch scan (wave-1 scheduled, persistent);
// blocks 32..1055 = GEMM tiles feeding the scan through chunk counters.
// ---------------------------------------------------------------------------
__global__ __launch_bounds__(256) void fused(
    const float* __restrict__ input,
    const float* __restrict__ z0, const float* __restrict__ v0,
    const float* __restrict__ i0,
    float* __restrict__ out, float* __restrict__ zf,
    float* __restrict__ vf, float* __restrict__ sf)
{
    extern __shared__ float dynsmem[];
    if (blockIdx.x < NSCAN)
        scan_body(dynsmem, z0, v0, i0, out, zf, vf, sf);
    else
        gemm_body(dynsmem, blockIdx.x - NSCAN, input, out);
}

// ---------------------------------------------------------------------------
extern "C" void kernel_launch(void* const* d_in, const int* in_sizes, int n_in,
                              void* d_out, int out_size) {
    const float* input = (const float*)d_in[0];  // (T, B, IN)
    const float* z0    = (const float*)d_in[1];  // (B, H)
    const float* v0    = (const float*)d_in[2];
    const float* i0    = (const float*)d_in[3];
    const float* Wi    = (const float*)d_in[4];  // (H, IN)
    const float* Wr    = (const float*)d_in[5];  // (H, H)

    float* out = (float*)d_out;                         // (T, B, H) spikes
    float* zf  = out + (size_t)T_STEPS * BATCH * HID;   // (B, H)
    float* vf  = zf + BATCH * HID;
    float* sf  = vf + BATCH * HID;

    const int smem_bytes = NROW * HSM * (int)sizeof(float);   // ~161 KB
    cudaFuncSetAttribute(fused, cudaFuncAttributeMaxDynamicSharedMemorySize,
                         smem_bytes);

    transpose_weights<<<HID, HID>>>(Wi, Wr);
    fused<<<NSCAN + GEMM_CTAS, 256, smem_bytes>>>(input, z0, v0, i0,
                                                  out, zf, vf, sf);
}